// round 14
// baseline (speedup 1.0000x reference)
#include <cuda_runtime.h>
#include <cstdint>

#define NF     12
#define NPAIR  66
#define NCOMB  781
#define NCOLS  793
#define NROWS  32768
#define WPB    4            // warps per block
#define RPW    4            // rows per warp
#define NVAL   80           // slots: 0..11 s_i, 12..77 pairs, 78 = 1.0, pad

// pair id, lexicographic i<j
constexpr int pid(int i, int j) { return i * (2 * NF - i - 1) / 2 + (j - i - 1); }

// ---------------------------------------------------------------------------
// Combo table: two 16-bit BYTE offsets into val[NVAL][4] (16 B per slot).
// combo value p = val[a][r] * val[b][r]; q = 1 - p via FFMA negate modifier.
// ---------------------------------------------------------------------------
struct CTbl { uint32_t v[NCOMB]; };
struct PTbl { uint32_t v[NPAIR]; };

constexpr CTbl make_ctbl() {
    CTbl t{};
    int p = 0;
    for (int i = 0; i < NF; ++i)                    // size 2: P2 * 1
        for (int j = i + 1; j < NF; ++j)
            t.v[p++] = (uint32_t)((12 + pid(i, j)) * 16)
                     | ((uint32_t)(78 * 16) << 16);
    for (int i = 0; i < NF; ++i)                    // size 3: P2(i,j) * s_k
        for (int j = i + 1; j < NF; ++j)
            for (int k = j + 1; k < NF; ++k)
                t.v[p++] = (uint32_t)((12 + pid(i, j)) * 16)
                         | ((uint32_t)(k * 16) << 16);
    for (int i = 0; i < NF; ++i)                    // size 4: P2(i,j) * P2(k,l)
        for (int j = i + 1; j < NF; ++j)
            for (int k = j + 1; k < NF; ++k)
                for (int l = k + 1; l < NF; ++l)
                    t.v[p++] = (uint32_t)((12 + pid(i, j)) * 16)
                             | ((uint32_t)((12 + pid(k, l)) * 16) << 16);
    return t;
}
constexpr PTbl make_ptbl() {
    PTbl t{};
    int p = 0;
    for (int i = 0; i < NF; ++i)
        for (int j = i + 1; j < NF; ++j)
            t.v[p++] = (uint32_t)i | ((uint32_t)j << 8);
    return t;
}

__device__ const CTbl d_ct = make_ctbl();
__device__ const PTbl d_pt = make_ptbl();

__device__ __forceinline__ float lg2a(float x) {
    float r; asm("lg2.approx.f32 %0,%1;" : "=f"(r) : "f"(x)); return r;
}
__device__ __forceinline__ float ex2a(float x) {
    float r; asm("ex2.approx.f32 %0,%1;" : "=f"(r) : "f"(x)); return r;
}
__device__ __forceinline__ float ss(float a, float b, float inv) {
    // 1 - (1 - a*b)^inv ; FFMA negate modifier makes the -a free
    return 1.0f - ex2a(lg2a(fmaf(-a, b, 1.0f)) * inv);
}

// ---------------------------------------------------------------------------
// Warp owns 4 rows; val[slot] is 16 B -> one LDS.128 per operand covers all
// 4 rows. Decode + LDS issue amortized 4x. 128-thread blocks keep 12
// blocks/SM resident despite ~40 regs. Streaming stores (write-once output).
// ---------------------------------------------------------------------------
__global__ __launch_bounds__(128)
void schweizer_kernel(const float* __restrict__ x,
                      const float* __restrict__ lam_p,
                      float* __restrict__ out)
{
    __shared__ __align__(16) float val[WPB][NVAL][RPW];

    const int lane = threadIdx.x & 31;
    const int wrp  = threadIdx.x >> 5;
    const int r0   = (blockIdx.x * WPB + wrp) * RPW;

    const float lam = __ldg(lam_p);
    const float inv = 1.0f / lam;

    float (*v)[RPW] = val[wrp];

    // ---- prologue: s_i for 4 rows + passthrough ----------------------------
    #pragma unroll
    for (int e = lane; e < RPW * NF; e += 32) {          // 48 coalesced loads
        const float xv = __ldg(x + (size_t)r0 * NF + e);
        const int f = e % NF, r = e / NF;
        v[f][r] = 1.0f - ex2a(lg2a(1.0f - xv) * lam);
        __stcs(out + (size_t)(r0 + r) * NCOLS + f, xv);
    }
    if (lane < RPW) v[78][lane] = 1.0f;                  // sentinel
    __syncwarp();

    // ---- 66 pairwise products (vectorized over 4 rows) ---------------------
    #pragma unroll
    for (int p = lane; p < NPAIR; p += 32) {
        const uint32_t w = __ldg(&d_pt.v[p]);
        const float4 a = *(const float4*)v[w & 0xFFu];
        const float4 b = *(const float4*)v[w >> 8];
        float4 r4;
        r4.x = a.x * b.x;  r4.y = a.y * b.y;
        r4.z = a.z * b.z;  r4.w = a.w * b.w;
        *(float4*)v[12 + p] = r4;
    }
    __syncwarp();

    // ---- main sweep: 24 full 32-column groups + 13-column tail -------------
    const char* vb = (const char*)v;
    float* __restrict__ o0 = out + (size_t)r0 * NCOLS + NF;
    float* __restrict__ o1 = o0 + NCOLS;
    float* __restrict__ o2 = o1 + NCOLS;
    float* __restrict__ o3 = o2 + NCOLS;

    #pragma unroll 4
    for (int k = 0; k < 24; ++k) {
        const int c = k * 32 + lane;
        const uint32_t w = __ldg(&d_ct.v[c]);
        const float4 a = *(const float4*)(vb + (w & 0xFFFFu));
        const float4 b = *(const float4*)(vb + (w >> 16));
        __stcs(o0 + c, ss(a.x, b.x, inv));
        __stcs(o1 + c, ss(a.y, b.y, inv));
        __stcs(o2 + c, ss(a.z, b.z, inv));
        __stcs(o3 + c, ss(a.w, b.w, inv));
    }
    if (lane < NCOMB - 768) {                            // cols 768..780
        const int c = 768 + lane;
        const uint32_t w = __ldg(&d_ct.v[c]);
        const float4 a = *(const float4*)(vb + (w & 0xFFFFu));
        const float4 b = *(const float4*)(vb + (w >> 16));
        __stcs(o0 + c, ss(a.x, b.x, inv));
        __stcs(o1 + c, ss(a.y, b.y, inv));
        __stcs(o2 + c, ss(a.z, b.z, inv));
        __stcs(o3 + c, ss(a.w, b.w, inv));
    }
}

extern "C" void kernel_launch(void* const* d_in, const int* in_sizes, int n_in,
                              void* d_out, int out_size)
{
    const float* x   = (const float*)d_in[0];
    const float* lam = (const float*)d_in[1];
    float*       out = (float*)d_out;

    schweizer_kernel<<<NROWS / (WPB * RPW), WPB * 32>>>(x, lam, out);
}